// round 1
// baseline (speedup 1.0000x reference)
#include <cuda_runtime.h>

// Detection_78477642432928 — YOLO decode head
// x: (64, 255, 52, 52) f32  ->  out: (64, 8112, 85) f32
//   pred = x.reshape(B,3,85,G,G).transpose(0,1,3,4,2)
//   c==0: (sigmoid+gx)*stride ; c==1: (sigmoid+gy)*stride
//   c==2: exp*anchor_w        ; c==3: exp*anchor_h
//   c>=4: sigmoid
// stride = 416/52 = 8; anchors scaled by stride then re-multiplied -> raw anchors.

#define G_DIM   52
#define GG      2704          // 52*52
#define NA      3
#define NC      85            // 5 + 80
#define TILE    128
#define NTILES  22            // ceil(2704/128); last tile has 16 positions
#define PITCH   129           // smem pitch to break c-stride bank conflicts

__device__ __forceinline__ float fsigmoid(float t) {
    return 1.0f / (1.0f + __expf(-t));
}

__global__ __launch_bounds__(256, 1)
void det_decode_kernel(const float* __restrict__ x, float* __restrict__ out) {
    __shared__ float s[NC * PITCH];

    const int bx    = blockIdx.x;
    const int tile  = bx % NTILES;
    const int a     = (bx / NTILES) % NA;
    const int b     = bx / (NTILES * NA);
    const int tstart = tile * TILE;
    const int nvalid = (tstart + TILE <= GG) ? TILE : (GG - tstart);  // 128 or 16
    const int tid   = threadIdx.x;

    // raw anchors (scaled/stride * stride cancels)
    const float aw = (a == 0) ? 10.0f : ((a == 1) ? 16.0f : 33.0f);
    const float ah = (a == 0) ? 13.0f : ((a == 1) ? 30.0f : 23.0f);

    const float* __restrict__ xin =
        x + (size_t)((b * NA + a) * NC) * GG + tstart;

    // ---- Load phase: 85 channel rows x nvalid floats, coalesced float4 ----
    const int nvec = nvalid >> 2;            // 32 or 4 float4 per row
    for (int i = tid; i < NC * (TILE / 4); i += 256) {
        const int c = i >> 5;                // i / 32
        const int v = i & 31;                // i % 32
        if (v < nvec) {
            float4 val = *(const float4*)(xin + (size_t)c * GG + (v << 2));
            float r[4] = {val.x, val.y, val.z, val.w};
            float o[4];
            #pragma unroll
            for (int k = 0; k < 4; k++) {
                const int sp = tstart + (v << 2) + k;   // spatial index in [0,2704)
                const float t = r[k];
                float res;
                if (c == 0) {
                    res = (fsigmoid(t) + (float)(sp % G_DIM)) * 8.0f;
                } else if (c == 1) {
                    res = (fsigmoid(t) + (float)(sp / G_DIM)) * 8.0f;
                } else if (c == 2) {
                    res = __expf(t) * aw;
                } else if (c == 3) {
                    res = __expf(t) * ah;
                } else {
                    res = fsigmoid(t);      // conf (c==4) and classes (c>=5)
                }
                o[k] = res;
            }
            const int p = v << 2;
            s[c * PITCH + p + 0] = o[0];
            s[c * PITCH + p + 1] = o[1];
            s[c * PITCH + p + 2] = o[2];
            s[c * PITCH + p + 3] = o[3];
        }
    }
    __syncthreads();

    // ---- Write phase: nvalid*85 floats are CONTIGUOUS in out; float4 stores ----
    float* __restrict__ optr =
        out + (size_t)((b * NA + a) * GG + tstart) * NC;
    const int total4 = (nvalid * NC) >> 2;   // 2720 or 340 (both exact)
    for (int i = tid; i < total4; i += 256) {
        const int j = i << 2;
        float4 w;
        {
            const int j0 = j;     w.x = s[(j0 % NC) * PITCH + (j0 / NC)];
            const int j1 = j + 1; w.y = s[(j1 % NC) * PITCH + (j1 / NC)];
            const int j2 = j + 2; w.z = s[(j2 % NC) * PITCH + (j2 / NC)];
            const int j3 = j + 3; w.w = s[(j3 % NC) * PITCH + (j3 / NC)];
        }
        ((float4*)optr)[i] = w;
    }
}

extern "C" void kernel_launch(void* const* d_in, const int* in_sizes, int n_in,
                              void* d_out, int out_size) {
    const float* x = (const float*)d_in[0];
    float* out = (float*)d_out;
    const int B = 64;
    const int nblocks = B * NA * NTILES;    // 4224
    det_decode_kernel<<<nblocks, 256>>>(x, out);
}